// round 5
// baseline (speedup 1.0000x reference)
#include <cuda_runtime.h>
#include <cuda_fp16.h>
#include <cstdint>

#define TT 1024
#define BB 64
#define HH 512
#define RR (TT*BB)              // 65536 rows
#define RES ((size_t)RR*HH)
#define BH (BB*HH)

// ---------------- device scratch ----------------
__device__ __half g_xh[(size_t)RR*512];      // x in fp16, k-permuted
__device__ __half g_hy0h[(size_t)RR*512];    // layer-0 hy in fp16, k-permuted
__device__ __half g_wp[2][2048*512];         // permuted+converted weights
__device__ float  g_hhp[2][BB*2048];         // h0@Whh^T + b_ih + b_hh, cols p=4h+gate

// ---------------- helpers ----------------
__device__ __forceinline__ uint32_t smem_u32(const void* p){
    uint32_t a; asm("{ .reg .u64 t; cvta.to.shared.u64 t, %1; cvt.u32.u64 %0, t; }" : "=r"(a) : "l"(p)); return a;
}
__device__ __forceinline__ float ex2f(float x){ float r; asm("ex2.approx.f32 %0,%1;" : "=f"(r):"f"(x)); return r; }
__device__ __forceinline__ float rcpf(float x){ float r; asm("rcp.approx.f32 %0,%1;" : "=f"(r):"f"(x)); return r; }
__device__ __forceinline__ float sigmf(float x){ return rcpf(1.0f + ex2f(-1.4426950408889634f*x)); }
__device__ __forceinline__ float tanhf2(float x){ return 1.0f - 2.0f*rcpf(1.0f + ex2f(2.8853900817779268f*x)); }

__device__ __forceinline__ void cpa16(uint32_t dst, const void* src){
    asm volatile("cp.async.cg.shared.global [%0], [%1], 16;" :: "r"(dst), "l"(src) : "memory");
}
#define CP_COMMIT() asm volatile("cp.async.commit_group;" ::: "memory")

__device__ __forceinline__ void mma16(float* c, const uint32_t* a, const uint32_t* b){
    asm volatile("mma.sync.aligned.m16n8k16.row.col.f32.f16.f16.f32 "
                 "{%0,%1,%2,%3}, {%4,%5,%6,%7}, {%8,%9}, {%0,%1,%2,%3};"
                 : "+f"(c[0]),"+f"(c[1]),"+f"(c[2]),"+f"(c[3])
                 : "r"(a[0]),"r"(a[1]),"r"(a[2]),"r"(a[3]), "r"(b[0]),"r"(b[1]));
}

__device__ __forceinline__ uint32_t h2u(const __half2 h){
    union { __half2 h2; uint32_t u; } cv; cv.h2 = h; return cv.u;
}

// k-group permutation: 16 floats -> 16 halves, pos 4t+j holds k = 2t + (j>>1)*8 + (j&1)
__device__ __forceinline__ void pack_perm(const float4 f0, const float4 f1,
                                          const float4 f2, const float4 f3,
                                          uint4* o){
    __half2 p0 = __floats2half2_rn(f0.x, f0.y);
    __half2 p1 = __floats2half2_rn(f2.x, f2.y);
    __half2 p2 = __floats2half2_rn(f0.z, f0.w);
    __half2 p3 = __floats2half2_rn(f2.z, f2.w);
    __half2 p4 = __floats2half2_rn(f1.x, f1.y);
    __half2 p5 = __floats2half2_rn(f3.x, f3.y);
    __half2 p6 = __floats2half2_rn(f1.z, f1.w);
    __half2 p7 = __floats2half2_rn(f3.z, f3.w);
    o[0] = make_uint4(h2u(p0), h2u(p1), h2u(p2), h2u(p3));
    o[1] = make_uint4(h2u(p4), h2u(p5), h2u(p6), h2u(p7));
}

// position q within a 16-group holding feature k
__device__ __forceinline__ int perm_pos(int k){
    return (k & ~15) | ((((k&7)>>1))<<2) | (((k>>3)&1)<<1) | (k&1);
}

// ---------------- prep kernels ----------------
__global__ void conv_x(const float* __restrict__ x){
    int task = blockIdx.x*256 + threadIdx.x;        // row*32 + grp
    if (task >= RR*32) return;
    int row = task >> 5, grp = task & 31;
    const float4* s = (const float4*)(x + (size_t)row*512 + grp*16);
    uint4 o[2];
    pack_perm(s[0], s[1], s[2], s[3], o);
    uint4* d = (uint4*)(g_xh + (size_t)row*512 + grp*16);
    d[0] = o[0]; d[1] = o[1];
}

__global__ void conv_w(const float* __restrict__ wih0, const float* __restrict__ wih1){
    int p = blockIdx.x*8 + (threadIdx.x>>5), l = blockIdx.y, grp = threadIdx.x&31;
    const float* w = l ? wih1 : wih0;
    int grow = ((p&3)<<9) + (p>>2);
    const float4* s = (const float4*)(w + (size_t)grow*512 + grp*16);
    uint4 o[2];
    pack_perm(s[0], s[1], s[2], s[3], o);
    uint4* d = (uint4*)(&g_wp[l][(size_t)p*512 + grp*16]);
    d[0] = o[0]; d[1] = o[1];
}

__global__ void prep_hh(const float* __restrict__ h0,
                        const float* __restrict__ whh0, const float* __restrict__ bhh0, const float* __restrict__ bih0,
                        const float* __restrict__ whh1, const float* __restrict__ bhh1, const float* __restrict__ bih1){
    int p = blockIdx.x*4 + (threadIdx.x>>6), l = blockIdx.y, b = threadIdx.x&63;
    const float* whh = l ? whh1 : whh0;
    const float* bhh = l ? bhh1 : bhh0;
    const float* bih = l ? bih1 : bih0;
    int grow = ((p&3)<<9) + (p>>2);
    const float4* hr = (const float4*)(h0 + (size_t)(l*64 + b)*512);
    const float4* wr = (const float4*)(whh + (size_t)grow*512);
    float acc = 0.f;
#pragma unroll 4
    for (int k = 0; k < 128; k++){
        float4 h = hr[k], w = wr[k];
        acc += h.x*w.x + h.y*w.y + h.z*w.z + h.w*w.w;
    }
    g_hhp[l][b*2048 + p] = acc + bhh[grow] + bih[grow];
}

// ---------------- fused GEMM + LSTM epilogue ----------------
#define STG_B    32768                 // B tile offset inside a stage
#define STAGE_SZ 49152                 // 256*128 + 128*128 bytes
#define NSTAGE   4
#define SMEM_TOT (NSTAGE*STAGE_SZ)     // 196608

__global__ void __launch_bounds__(256,1)
lstm_gemm(const __half* __restrict__ Ah, const __half* __restrict__ Bh,
          const float* __restrict__ hhp, const float* __restrict__ c0l,
          float* __restrict__ outf, __half* __restrict__ outh,
          float* __restrict__ lasth, float* __restrict__ lastc)
{
    extern __shared__ char smem[];
    const uint32_t sb = smem_u32(smem);
    const int tid = threadIdx.x, wid = tid>>5, lane = tid&31;
    const int g = lane>>2, t = lane&3;
    const int wm = wid&3, wn = wid>>2;          // 4 x 2 warp grid, warp tile 64x64
    const int row0 = blockIdx.y*256, ncb = blockIdx.x*128, hbase = ncb>>2;

    // --- per-thread load constants ---
    const int lr = tid>>3, lc = tid&7;
    const __half* aSrc = Ah + (size_t)(row0+lr)*512 + lc*8;
    const __half* bSrc = Bh + (size_t)(ncb+lr)*512 + lc*8;
    const uint32_t ldOff = (uint32_t)(lr*128 + (((lc>>1) ^ (lr&3))<<5) + ((lc&1)<<4));

    auto issue = [&](int kc){
        uint32_t base = sb + (kc&(NSTAGE-1))*STAGE_SZ + ldOff;
        const __half* as = aSrc + kc*64;
        const __half* bs = bSrc + kc*64;
#pragma unroll
        for (int j = 0; j < 8; j++) cpa16(base + j*4096, as + j*(32*512));
#pragma unroll
        for (int j = 0; j < 4; j++) cpa16(base + STG_B + j*4096, bs + j*(32*512));
        CP_COMMIT();
    };

    issue(0); issue(1); issue(2);

    float acc[4][8][4];
#pragma unroll
    for (int a = 0; a < 4; a++)
#pragma unroll
        for (int b = 0; b < 8; b++)
#pragma unroll
            for (int c = 0; c < 4; c++) acc[a][b][c] = 0.f;

    // --- per-lane LDS constants ---
    const uint32_t gx  = (uint32_t)((g&3)<<5);
    const uint32_t aL0 = (uint32_t)((wm*64+g)*128 + t*8);
    const uint32_t bL0 = (uint32_t)(STG_B + (wn*64+g)*128 + t*8);

    for (int kc = 0; kc < 8; kc++){
        if (kc < 6)      asm volatile("cp.async.wait_group 2;" ::: "memory");
        else if (kc == 6) asm volatile("cp.async.wait_group 1;" ::: "memory");
        else              asm volatile("cp.async.wait_group 0;" ::: "memory");
        __syncthreads();
        if (kc + 3 < 8) issue(kc+3);

        const char* st = smem + (kc&(NSTAGE-1))*STAGE_SZ;
#pragma unroll
        for (int ks = 0; ks < 4; ks++){
            const uint32_t x = ((uint32_t)ks<<5) ^ gx;
            uint32_t a[4][4], b[8][2];
#pragma unroll
            for (int mt = 0; mt < 4; mt++){
                uint2 v0 = *(const uint2*)(st + aL0 + mt*2048 + x);
                uint2 v1 = *(const uint2*)(st + aL0 + mt*2048 + 1024 + x);
                a[mt][0] = v0.x; a[mt][2] = v0.y;
                a[mt][1] = v1.x; a[mt][3] = v1.y;
            }
#pragma unroll
            for (int nt = 0; nt < 8; nt++){
                uint2 v = *(const uint2*)(st + bL0 + nt*1024 + x);
                b[nt][0] = v.x; b[nt][1] = v.y;
            }
#pragma unroll
            for (int mt = 0; mt < 4; mt++)
#pragma unroll
                for (int nt = 0; nt < 8; nt++)
                    mma16(acc[mt][nt], a[mt], b[nt]);
        }
    }

    __syncthreads();   // stage smem now free for output staging

    float*  outS  = (float*) smem;   // [256][36] fp32 (padded)
    __half* outSh = (__half*)smem;   // [256][40] fp16 (padded)

#pragma unroll
    for (int mt = 0; mt < 4; mt++){
#pragma unroll
        for (int nt = 0; nt < 8; nt++){
            int rl0 = wm*64 + mt*16 + g;
            int rl1 = rl0 + 8;
            int pl  = wn*64 + nt*8 + 2*t;
            const float2 hbE = *(const float2*)(hhp + (rl0&63)*2048 + ncb + pl);
            const float2 hbO = *(const float2*)(hhp + (rl1&63)*2048 + ncb + pl);
            float d0 = acc[mt][nt][0] + hbE.x;
            float d1 = acc[mt][nt][1] + hbE.y;
            float d2 = acc[mt][nt][2] + hbO.x;
            float d3 = acc[mt][nt][3] + hbO.y;
            float s0 = (t&1) ? d0 : d2;  float r0 = __shfl_xor_sync(0xffffffffu, s0, 1);
            float s1 = (t&1) ? d1 : d3;  float r1 = __shfl_xor_sync(0xffffffffu, s1, 1);
            float ig, fg, gg, og; int rr;
            if (!(t&1)){ ig = d0; fg = d1; gg = r0; og = r1; rr = rl0; }
            else       { ig = r0; fg = r1; gg = d2; og = d3; rr = rl1; }
            int hl = wn*16 + nt*2 + (t>>1);
            float c0v = c0l[(rr&63)*512 + hbase + hl];
            float cy = sigmf(fg)*c0v + sigmf(ig)*tanhf2(gg);
            float hy = sigmf(og)*tanhf2(cy);
            if (outf) outS[rr*36 + hl] = hy;
            else      outSh[rr*40 + perm_pos(hl)] = __float2half_rn(hy);
            int grow_ = row0 + rr;
            if (grow_ >= RR - BB){
                int b = grow_ & 63;
                lasth[b*512 + hbase + hl] = hy;
                lastc[b*512 + hbase + hl] = cy;
            }
        }
    }
    __syncthreads();

    if (outf){
#pragma unroll
        for (int i = 0; i < 8; i++){
            int idx = tid + i*256;
            int r = idx >> 3, j = idx & 7;
            float4 v = *(const float4*)(outS + r*36 + j*4);
            *(float4*)(outf + (size_t)(row0+r)*512 + hbase + j*4) = v;
        }
    } else {
#pragma unroll
        for (int i = 0; i < 4; i++){
            int idx = tid + i*256;
            int r = idx >> 2, j = idx & 3;
            uint4 v = *(const uint4*)(outSh + r*40 + j*8);
            *(uint4*)(outh + (size_t)(row0+r)*512 + hbase + j*8) = v;
        }
    }
}

// ---------------- launch ----------------
extern "C" void kernel_launch(void* const* d_in, const int* in_sizes, int n_in,
                              void* d_out, int out_size)
{
    (void)in_sizes; (void)n_in; (void)out_size;
    const float* x    = (const float*)d_in[0];
    const float* h0   = (const float*)d_in[1];
    const float* c0   = (const float*)d_in[2];
    const float* wih0 = (const float*)d_in[3];
    const float* whh0 = (const float*)d_in[4];
    const float* bih0 = (const float*)d_in[5];
    const float* bhh0 = (const float*)d_in[6];
    const float* wih1 = (const float*)d_in[7];
    const float* whh1 = (const float*)d_in[8];
    const float* bih1 = (const float*)d_in[9];
    const float* bhh1 = (const float*)d_in[10];
    float* out = (float*)d_out;

    static __half* xh_p = nullptr; static __half* hy0h_p = nullptr;
    static __half* wp0_p = nullptr; static __half* wp1_p = nullptr;
    static float* hhp0_p = nullptr; static float* hhp1_p = nullptr;
    if (!xh_p){
        cudaGetSymbolAddress((void**)&xh_p,   g_xh);
        cudaGetSymbolAddress((void**)&hy0h_p, g_hy0h);
        void* wp; cudaGetSymbolAddress(&wp, g_wp);
        wp0_p = (__half*)wp; wp1_p = wp0_p + 2048*512;
        void* hh; cudaGetSymbolAddress(&hh, g_hhp);
        hhp0_p = (float*)hh; hhp1_p = hhp0_p + BB*2048;
        cudaFuncSetAttribute(lstm_gemm, cudaFuncAttributeMaxDynamicSharedMemorySize, SMEM_TOT);
    }

    conv_x<<<(RR*32 + 255)/256, 256>>>(x);
    conv_w<<<dim3(256,2), 256>>>(wih0, wih1);
    prep_hh<<<dim3(512,2), 256>>>(h0, whh0, bhh0, bih0, whh1, bhh1, bih1);

    // layer 0: A = xh, B = wp0 -> hy0h (fp16, k-permuted), lasth[0], lastc[0]
    lstm_gemm<<<dim3(16,256), 256, SMEM_TOT>>>(xh_p, wp0_p, hhp0_p, c0,
                                               nullptr, hy0h_p,
                                               out + RES, out + RES + 2*(size_t)BH);
    // layer 1: A = hy0h, B = wp1 -> out (fp32), lasth[1], lastc[1]
    lstm_gemm<<<dim3(16,256), 256, SMEM_TOT>>>(hy0h_p, wp1_p, hhp1_p, c0 + BH,
                                               out, nullptr,
                                               out + RES + (size_t)BH, out + RES + 3*(size_t)BH);
}

// round 6
// speedup vs baseline: 1.9618x; 1.9618x over previous
#include <cuda_runtime.h>
#include <cuda_fp16.h>
#include <cstdint>

#define TT 1024
#define BB 64
#define HH 512
#define RR (TT*BB)              // 65536 rows
#define RES ((size_t)RR*HH)
#define BH (BB*HH)

// ---------------- device scratch ----------------
__device__ __half g_xh[(size_t)RR*512];      // x in fp16 (natural order)
__device__ __half g_hy0h[(size_t)RR*512];    // layer-0 hy in fp16 (natural order)
__device__ __half g_wp[2][2048*512];         // gate-permuted rows (p=4h+gate), natural k
__device__ float  g_hhp[2][BB*2048];         // h0@Whh^T + b_ih + b_hh, cols p=4h+gate

// ---------------- helpers ----------------
__device__ __forceinline__ uint32_t smem_u32(const void* p){
    uint32_t a; asm("{ .reg .u64 t; cvta.to.shared.u64 t, %1; cvt.u32.u64 %0, t; }" : "=r"(a) : "l"(p)); return a;
}
__device__ __forceinline__ float ex2f(float x){ float r; asm("ex2.approx.f32 %0,%1;" : "=f"(r):"f"(x)); return r; }
__device__ __forceinline__ float rcpf(float x){ float r; asm("rcp.approx.f32 %0,%1;" : "=f"(r):"f"(x)); return r; }
__device__ __forceinline__ float sigmf(float x){ return rcpf(1.0f + ex2f(-1.4426950408889634f*x)); }
__device__ __forceinline__ float tanhf2(float x){ return 1.0f - 2.0f*rcpf(1.0f + ex2f(2.8853900817779268f*x)); }

__device__ __forceinline__ void cpa16(uint32_t dst, const void* src){
    asm volatile("cp.async.cg.shared.global [%0], [%1], 16;" :: "r"(dst), "l"(src) : "memory");
}
#define CP_COMMIT() asm volatile("cp.async.commit_group;" ::: "memory")

__device__ __forceinline__ void mma16(float* c, const uint32_t* a, const uint32_t* b){
    asm volatile("mma.sync.aligned.m16n8k16.row.col.f32.f16.f16.f32 "
                 "{%0,%1,%2,%3}, {%4,%5,%6,%7}, {%8,%9}, {%0,%1,%2,%3};"
                 : "+f"(c[0]),"+f"(c[1]),"+f"(c[2]),"+f"(c[3])
                 : "r"(a[0]),"r"(a[1]),"r"(a[2]),"r"(a[3]), "r"(b[0]),"r"(b[1]));
}
__device__ __forceinline__ void ldsm4(uint32_t* r, uint32_t addr){
    asm volatile("ldmatrix.sync.aligned.m8n8.x4.shared.b16 {%0,%1,%2,%3}, [%4];"
                 : "=r"(r[0]),"=r"(r[1]),"=r"(r[2]),"=r"(r[3]) : "r"(addr));
}
__device__ __forceinline__ uint32_t h2u(const __half2 h){
    union { __half2 h2; uint32_t u; } cv; cv.h2 = h; return cv.u;
}

// natural-order pack: 16 floats -> 16 halves (2 uint4)
__device__ __forceinline__ void pack_nat(const float4 f0, const float4 f1,
                                         const float4 f2, const float4 f3, uint4* o){
    o[0] = make_uint4(h2u(__floats2half2_rn(f0.x,f0.y)), h2u(__floats2half2_rn(f0.z,f0.w)),
                      h2u(__floats2half2_rn(f1.x,f1.y)), h2u(__floats2half2_rn(f1.z,f1.w)));
    o[1] = make_uint4(h2u(__floats2half2_rn(f2.x,f2.y)), h2u(__floats2half2_rn(f2.z,f2.w)),
                      h2u(__floats2half2_rn(f3.x,f3.y)), h2u(__floats2half2_rn(f3.z,f3.w)));
}

// ---------------- prep kernels ----------------
__global__ void conv_x(const float* __restrict__ x){
    int task = blockIdx.x*256 + threadIdx.x;        // row*32 + grp
    if (task >= RR*32) return;
    int row = task >> 5, grp = task & 31;
    const float4* s = (const float4*)(x + (size_t)row*512 + grp*16);
    uint4 o[2];
    pack_nat(s[0], s[1], s[2], s[3], o);
    uint4* d = (uint4*)(g_xh + (size_t)row*512 + grp*16);
    d[0] = o[0]; d[1] = o[1];
}

__global__ void conv_w(const float* __restrict__ wih0, const float* __restrict__ wih1){
    int p = blockIdx.x*8 + (threadIdx.x>>5), l = blockIdx.y, grp = threadIdx.x&31;
    const float* w = l ? wih1 : wih0;
    int grow = ((p&3)<<9) + (p>>2);
    const float4* s = (const float4*)(w + (size_t)grow*512 + grp*16);
    uint4 o[2];
    pack_nat(s[0], s[1], s[2], s[3], o);
    uint4* d = (uint4*)(&g_wp[l][(size_t)p*512 + grp*16]);
    d[0] = o[0]; d[1] = o[1];
}

// tiled: block = 16 p-rows x 64 b; h0 k-slice staged in smem transposed [k][b]
__global__ void __launch_bounds__(1024,1) prep_hh(
        const float* __restrict__ h0,
        const float* __restrict__ whh0, const float* __restrict__ bhh0, const float* __restrict__ bih0,
        const float* __restrict__ whh1, const float* __restrict__ bhh1, const float* __restrict__ bih1){
    __shared__ float sh[128][65];
    int l = blockIdx.y;
    int tid = threadIdx.x;
    int pi = tid >> 6, b = tid & 63;
    int p = blockIdx.x*16 + pi;
    const float* whh = l ? whh1 : whh0;
    const float* bhh = l ? bhh1 : bhh0;
    const float* bih = l ? bih1 : bih0;
    int grow = ((p&3)<<9) + (p>>2);
    const float* wr = whh + (size_t)grow*512;
    float acc = 0.f;
    for (int kb = 0; kb < 4; kb++){
        // load h0 slice [64 b][128 k] -> sh[k][b]
        #pragma unroll
        for (int i = 0; i < 2; i++){
            int f4 = tid*2 + i;                 // 0..2047
            int bb = f4 >> 5, kq = f4 & 31;
            float4 v = *(const float4*)(h0 + (size_t)(l*64+bb)*512 + kb*128 + kq*4);
            sh[kq*4+0][bb] = v.x; sh[kq*4+1][bb] = v.y;
            sh[kq*4+2][bb] = v.z; sh[kq*4+3][bb] = v.w;
        }
        __syncthreads();
        const float4* wv = (const float4*)(wr + kb*128);
        #pragma unroll 8
        for (int k4 = 0; k4 < 32; k4++){
            float4 w = wv[k4];
            acc += w.x*sh[k4*4+0][b] + w.y*sh[k4*4+1][b]
                 + w.z*sh[k4*4+2][b] + w.w*sh[k4*4+3][b];
        }
        __syncthreads();
    }
    g_hhp[l][b*2048 + p] = acc + bhh[grow] + bih[grow];
}

// ---------------- fused GEMM + LSTM epilogue ----------------
// CTA tile 128x128, 8 warps (2m x 4n), warp tile 64x32, K-chunk 64, 3 stages
#define STG_B    16384                 // B offset inside a stage (A = 128*128B)
#define STAGE_SZ 32768
#define SMEM_TOT (3*STAGE_SZ)          // 98304

__global__ void __launch_bounds__(256,2)
lstm_gemm(const __half* __restrict__ Ah, const __half* __restrict__ Bh,
          const float* __restrict__ hhp, const float* __restrict__ c0l,
          float* __restrict__ outf, __half* __restrict__ outh,
          float* __restrict__ lasth, float* __restrict__ lastc)
{
    extern __shared__ char smem[];
    const uint32_t sb = smem_u32(smem);
    const int tid = threadIdx.x, wid = tid>>5, lane = tid&31;
    const int g = lane>>2, t = lane&3;
    const int wm = wid&1, wn = wid>>1;          // 2 x 4 warp grid
    const int row0 = blockIdx.y*128, ncb = blockIdx.x*128, hbase = ncb>>2;

    // --- cp.async per-thread constants (r = tid>>3 covers 0..31; +j*32 rows) ---
    const int lr = tid>>3, lc = tid&7;
    const __half* aSrc = Ah + (size_t)(row0+lr)*512 + lc*8;
    const __half* bSrc = Bh + (size_t)(ncb+lr)*512 + lc*8;
    const uint32_t stOff = (uint32_t)(lr*128 + ((lc ^ (lr&7))<<4));

    auto issue = [&](int kc){
        uint32_t base = sb + (kc%3)*STAGE_SZ + stOff;
        const __half* as = aSrc + kc*64;
        const __half* bs = bSrc + kc*64;
#pragma unroll
        for (int j = 0; j < 4; j++) cpa16(base + j*4096, as + j*(32*512));
#pragma unroll
        for (int j = 0; j < 4; j++) cpa16(base + STG_B + j*4096, bs + j*(32*512));
        CP_COMMIT();
    };

    issue(0); issue(1);

    float acc[4][4][4];
#pragma unroll
    for (int a = 0; a < 4; a++)
#pragma unroll
        for (int b = 0; b < 4; b++)
#pragma unroll
            for (int c = 0; c < 4; c++) acc[a][b][c] = 0.f;

    // --- ldmatrix per-lane constants ---
    const int lrow = lane&7, grp = lane>>3;
    const uint32_t aBase = (uint32_t)((wm*64 + (grp&1)*8 + lrow)*128);
    const uint32_t bBase = (uint32_t)(STG_B + (wn*32 + (grp>>1)*8 + lrow)*128);
    const int aCsel = grp>>1, bCsel = grp&1;

    for (int kc = 0; kc < 8; kc++){
        if (kc == 7) asm volatile("cp.async.wait_group 0;" ::: "memory");
        else         asm volatile("cp.async.wait_group 1;" ::: "memory");
        __syncthreads();
        if (kc + 2 < 8) issue(kc+2);

        const uint32_t st = sb + (kc%3)*STAGE_SZ;
#pragma unroll
        for (int ks = 0; ks < 4; ks++){
            const uint32_t va = (uint32_t)(((2*ks + aCsel) ^ lrow) << 4);
            const uint32_t vb = (uint32_t)(((2*ks + bCsel) ^ lrow) << 4);
            uint32_t a[4][4], b[4][2];
#pragma unroll
            for (int mt = 0; mt < 4; mt++)
                ldsm4(a[mt], st + aBase + mt*2048 + va);
#pragma unroll
            for (int pr = 0; pr < 2; pr++){
                uint32_t q[4];
                ldsm4(q, st + bBase + pr*2048 + vb);
                b[pr*2][0] = q[0]; b[pr*2][1] = q[1];
                b[pr*2+1][0] = q[2]; b[pr*2+1][1] = q[3];
            }
#pragma unroll
            for (int mt = 0; mt < 4; mt++)
#pragma unroll
                for (int nt = 0; nt < 4; nt++)
                    mma16(acc[mt][nt], a[mt], b[nt]);
        }
    }

    __syncthreads();   // stage smem now free for output staging

    float*  outS  = (float*) smem;   // [128][36] fp32 (padded)
    __half* outSh = (__half*)smem;   // [128][40] fp16 (padded)

#pragma unroll
    for (int mt = 0; mt < 4; mt++){
#pragma unroll
        for (int nt = 0; nt < 4; nt++){
            int rl0 = wm*64 + mt*16 + g;
            int rl1 = rl0 + 8;
            int pl  = wn*32 + nt*8 + 2*t;
            const float2 hbE = *(const float2*)(hhp + (rl0&63)*2048 + ncb + pl);
            const float2 hbO = *(const float2*)(hhp + (rl1&63)*2048 + ncb + pl);
            float d0 = acc[mt][nt][0] + hbE.x;
            float d1 = acc[mt][nt][1] + hbE.y;
            float d2 = acc[mt][nt][2] + hbO.x;
            float d3 = acc[mt][nt][3] + hbO.y;
            float s0 = (t&1) ? d0 : d2;  float r0 = __shfl_xor_sync(0xffffffffu, s0, 1);
            float s1 = (t&1) ? d1 : d3;  float r1 = __shfl_xor_sync(0xffffffffu, s1, 1);
            float ig, fg, gg, og; int rr;
            if (!(t&1)){ ig = d0; fg = d1; gg = r0; og = r1; rr = rl0; }
            else       { ig = r0; fg = r1; gg = d2; og = d3; rr = rl1; }
            int hl = wn*8 + nt*2 + (t>>1);
            float c0v = c0l[(rr&63)*512 + hbase + hl];
            float cy = sigmf(fg)*c0v + sigmf(ig)*tanhf2(gg);
            float hy = sigmf(og)*tanhf2(cy);
            if (outf) outS[rr*36 + hl] = hy;
            else      outSh[rr*40 + hl] = __float2half_rn(hy);
            int grow_ = row0 + rr;
            if (grow_ >= RR - BB){
                int b = grow_ & 63;
                lasth[b*512 + hbase + hl] = hy;
                lastc[b*512 + hbase + hl] = cy;
            }
        }
    }
    __syncthreads();

    if (outf){
#pragma unroll
        for (int i = 0; i < 4; i++){
            int idx = tid + i*256;
            int r = idx >> 3, j = idx & 7;
            float4 v = *(const float4*)(outS + r*36 + j*4);
            *(float4*)(outf + (size_t)(row0+r)*512 + hbase + j*4) = v;
        }
    } else {
#pragma unroll
        for (int i = 0; i < 2; i++){
            int idx = tid + i*256;
            int r = idx >> 2, j = idx & 3;
            uint4 v = *(const uint4*)(outSh + r*40 + j*8);
            *(uint4*)(outh + (size_t)(row0+r)*512 + hbase + j*8) = v;
        }
    }
}

// ---------------- launch ----------------
extern "C" void kernel_launch(void* const* d_in, const int* in_sizes, int n_in,
                              void* d_out, int out_size)
{
    (void)in_sizes; (void)n_in; (void)out_size;
    const float* x    = (const float*)d_in[0];
    const float* h0   = (const float*)d_in[1];
    const float* c0   = (const float*)d_in[2];
    const float* wih0 = (const float*)d_in[3];
    const float* whh0 = (const float*)d_in[4];
    const float* bih0 = (const float*)d_in[5];
    const float* bhh0 = (const float*)d_in[6];
    const float* wih1 = (const float*)d_in[7];
    const float* whh1 = (const float*)d_in[8];
    const float* bih1 = (const float*)d_in[9];
    const float* bhh1 = (const float*)d_in[10];
    float* out = (float*)d_out;

    static __half* xh_p = nullptr; static __half* hy0h_p = nullptr;
    static __half* wp0_p = nullptr; static __half* wp1_p = nullptr;
    static float* hhp0_p = nullptr; static float* hhp1_p = nullptr;
    if (!xh_p){
        cudaGetSymbolAddress((void**)&xh_p,   g_xh);
        cudaGetSymbolAddress((void**)&hy0h_p, g_hy0h);
        void* wp; cudaGetSymbolAddress(&wp, g_wp);
        wp0_p = (__half*)wp; wp1_p = wp0_p + 2048*512;
        void* hh; cudaGetSymbolAddress(&hh, g_hhp);
        hhp0_p = (float*)hh; hhp1_p = hhp0_p + BB*2048;
        cudaFuncSetAttribute(lstm_gemm, cudaFuncAttributeMaxDynamicSharedMemorySize, SMEM_TOT);
    }

    conv_x<<<(RR*32 + 255)/256, 256>>>(x);
    conv_w<<<dim3(256,2), 256>>>(wih0, wih1);
    prep_hh<<<dim3(128,2), 1024>>>(h0, whh0, bhh0, bih0, whh1, bhh1, bih1);

    // layer 0: A = xh, B = wp0 -> hy0h (fp16), lasth[0], lastc[0]
    lstm_gemm<<<dim3(16,512), 256, SMEM_TOT>>>(xh_p, wp0_p, hhp0_p, c0,
                                               nullptr, hy0h_p,
                                               out + RES, out + RES + 2*(size_t)BH);
    // layer 1: A = hy0h, B = wp1 -> out (fp32), lasth[1], lastc[1]
    lstm_gemm<<<dim3(16,512), 256, SMEM_TOT>>>(hy0h_p, wp1_p, hhp1_p, c0 + BH,
                                               out, nullptr,
                                               out + RES + (size_t)BH, out + RES + 3*(size_t)BH);
}

// round 8
// speedup vs baseline: 2.0259x; 1.0327x over previous
#include <cuda_runtime.h>
#include <cuda_fp16.h>
#include <cstdint>

#define TT 1024
#define BB 64
#define HH 512
#define RR (TT*BB)              // 65536 rows
#define RES ((size_t)RR*HH)
#define BH (BB*HH)

// ---------------- device scratch ----------------
__device__ __half g_xh[(size_t)RR*512];      // x in fp16 (natural order)
__device__ __half g_hy0h[(size_t)RR*512];    // layer-0 hy in fp16 (natural order)
__device__ __half g_wp[2][2048*512];         // gate-permuted rows (p=4h+gate), natural k
__device__ float  g_hhp[2][BB*2048];         // h0@Whh^T + b_ih + b_hh, cols p=4h+gate

// ---------------- helpers ----------------
__device__ __forceinline__ uint32_t smem_u32(const void* p){
    uint32_t a; asm("{ .reg .u64 t; cvta.to.shared.u64 t, %1; cvt.u32.u64 %0, t; }" : "=r"(a) : "l"(p)); return a;
}
__device__ __forceinline__ float ex2f(float x){ float r; asm("ex2.approx.f32 %0,%1;" : "=f"(r):"f"(x)); return r; }
__device__ __forceinline__ float rcpf(float x){ float r; asm("rcp.approx.f32 %0,%1;" : "=f"(r):"f"(x)); return r; }
__device__ __forceinline__ float sigmf(float x){ return rcpf(1.0f + ex2f(-1.4426950408889634f*x)); }
__device__ __forceinline__ float tanhf2(float x){ return 1.0f - 2.0f*rcpf(1.0f + ex2f(2.8853900817779268f*x)); }

__device__ __forceinline__ void cpa16(uint32_t dst, const void* src){
    asm volatile("cp.async.cg.shared.global [%0], [%1], 16;" :: "r"(dst), "l"(src) : "memory");
}
#define CP_COMMIT() asm volatile("cp.async.commit_group;" ::: "memory")

__device__ __forceinline__ void mma16(float* c, const uint32_t* a, const uint32_t* b){
    asm volatile("mma.sync.aligned.m16n8k16.row.col.f32.f16.f16.f32 "
                 "{%0,%1,%2,%3}, {%4,%5,%6,%7}, {%8,%9}, {%0,%1,%2,%3};"
                 : "+f"(c[0]),"+f"(c[1]),"+f"(c[2]),"+f"(c[3])
                 : "r"(a[0]),"r"(a[1]),"r"(a[2]),"r"(a[3]), "r"(b[0]),"r"(b[1]));
}
__device__ __forceinline__ void ldsm4(uint32_t* r, uint32_t addr){
    asm volatile("ldmatrix.sync.aligned.m8n8.x4.shared.b16 {%0,%1,%2,%3}, [%4];"
                 : "=r"(r[0]),"=r"(r[1]),"=r"(r[2]),"=r"(r[3]) : "r"(addr));
}
__device__ __forceinline__ uint32_t h2u(const __half2 h){
    union { __half2 h2; uint32_t u; } cv; cv.h2 = h; return cv.u;
}

// natural-order pack: 16 floats -> 16 halves (2 uint4)
__device__ __forceinline__ void pack_nat(const float4 f0, const float4 f1,
                                         const float4 f2, const float4 f3, uint4* o){
    o[0] = make_uint4(h2u(__floats2half2_rn(f0.x,f0.y)), h2u(__floats2half2_rn(f0.z,f0.w)),
                      h2u(__floats2half2_rn(f1.x,f1.y)), h2u(__floats2half2_rn(f1.z,f1.w)));
    o[1] = make_uint4(h2u(__floats2half2_rn(f2.x,f2.y)), h2u(__floats2half2_rn(f2.z,f2.w)),
                      h2u(__floats2half2_rn(f3.x,f3.y)), h2u(__floats2half2_rn(f3.z,f3.w)));
}

// ---------------- prep kernels ----------------
__global__ void conv_x(const float* __restrict__ x){
    int task = blockIdx.x*256 + threadIdx.x;        // row*32 + grp
    if (task >= RR*32) return;
    int row = task >> 5, grp = task & 31;
    const float4* s = (const float4*)(x + (size_t)row*512 + grp*16);
    uint4 o[2];
    pack_nat(s[0], s[1], s[2], s[3], o);
    uint4* d = (uint4*)(g_xh + (size_t)row*512 + grp*16);
    d[0] = o[0]; d[1] = o[1];
}

__global__ void conv_w(const float* __restrict__ wih0, const float* __restrict__ wih1){
    int p = blockIdx.x*8 + (threadIdx.x>>5), l = blockIdx.y, grp = threadIdx.x&31;
    const float* w = l ? wih1 : wih0;
    int grow = ((p&3)<<9) + (p>>2);
    const float4* s = (const float4*)(w + (size_t)grow*512 + grp*16);
    uint4 o[2];
    pack_nat(s[0], s[1], s[2], s[3], o);
    uint4* d = (uint4*)(&g_wp[l][(size_t)p*512 + grp*16]);
    d[0] = o[0]; d[1] = o[1];
}

// tiled: block = 16 p-rows x 64 b; h0 k-slice staged in smem transposed [k][b]
__global__ void __launch_bounds__(1024,1) prep_hh(
        const float* __restrict__ h0,
        const float* __restrict__ whh0, const float* __restrict__ bhh0, const float* __restrict__ bih0,
        const float* __restrict__ whh1, const float* __restrict__ bhh1, const float* __restrict__ bih1){
    __shared__ float sh[128][65];
    int l = blockIdx.y;
    int tid = threadIdx.x;
    int pi = tid >> 6, b = tid & 63;
    int p = blockIdx.x*16 + pi;
    const float* whh = l ? whh1 : whh0;
    const float* bhh = l ? bhh1 : bhh0;
    const float* bih = l ? bih1 : bih0;
    int grow = ((p&3)<<9) + (p>>2);
    const float* wr = whh + (size_t)grow*512;
    float acc = 0.f;
    for (int kb = 0; kb < 4; kb++){
        #pragma unroll
        for (int i = 0; i < 2; i++){
            int f4 = tid*2 + i;                 // 0..2047
            int bb = f4 >> 5, kq = f4 & 31;
            float4 v = *(const float4*)(h0 + (size_t)(l*64+bb)*512 + kb*128 + kq*4);
            sh[kq*4+0][bb] = v.x; sh[kq*4+1][bb] = v.y;
            sh[kq*4+2][bb] = v.z; sh[kq*4+3][bb] = v.w;
        }
        __syncthreads();
        const float4* wv = (const float4*)(wr + kb*128);
        #pragma unroll 8
        for (int k4 = 0; k4 < 32; k4++){
            float4 w = wv[k4];
            acc += w.x*sh[k4*4+0][b] + w.y*sh[k4*4+1][b]
                 + w.z*sh[k4*4+2][b] + w.w*sh[k4*4+3][b];
        }
        __syncthreads();
    }
    g_hhp[l][b*2048 + p] = acc + bhh[grow] + bih[grow];
}

// ---------------- fused GEMM + LSTM epilogue ----------------
// CTA tile 128x128, 4 warps (2m x 2n), warp tile 64x64, K-chunk 64, 3 stages, 2 CTAs/SM
#define STG_B    16384                 // B offset inside a stage (A = 128*128B)
#define STAGE_SZ 32768
#define SMEM_TOT (3*STAGE_SZ)          // 98304

__global__ void __launch_bounds__(128,2)
lstm_gemm(const __half* __restrict__ Ah, const __half* __restrict__ Bh,
          const float* __restrict__ hhp, const float* __restrict__ c0l,
          float* __restrict__ outf, __half* __restrict__ outh,
          float* __restrict__ lasth, float* __restrict__ lastc)
{
    extern __shared__ char smem[];
    const uint32_t sb = smem_u32(smem);
    const int tid = threadIdx.x, wid = tid>>5, lane = tid&31;
    const int g = lane>>2, t = lane&3;
    const int wm = wid&1, wn = wid>>1;          // 2 x 2 warp grid, warp tile 64x64
    const int row0 = blockIdx.y*128, ncb = blockIdx.x*128, hbase = ncb>>2;

    // --- cp.async per-thread constants (lr covers 0..15; +j*16 rows) ---
    const int lr = tid>>3, lc = tid&7;
    const __half* aSrc = Ah + (size_t)(row0+lr)*512 + lc*8;
    const __half* bSrc = Bh + (size_t)(ncb+lr)*512 + lc*8;
    const uint32_t stOff = (uint32_t)(lr*128 + ((lc ^ (lr&7))<<4));

    auto issue = [&](int kc){
        uint32_t base = sb + (kc%3)*STAGE_SZ + stOff;
        const __half* as = aSrc + kc*64;
        const __half* bs = bSrc + kc*64;
#pragma unroll
        for (int j = 0; j < 8; j++) cpa16(base + j*2048, as + j*(16*512));
#pragma unroll
        for (int j = 0; j < 8; j++) cpa16(base + STG_B + j*2048, bs + j*(16*512));
        CP_COMMIT();
    };

    issue(0); issue(1);

    float acc[4][8][4];
#pragma unroll
    for (int a = 0; a < 4; a++)
#pragma unroll
        for (int b = 0; b < 8; b++)
#pragma unroll
            for (int c = 0; c < 4; c++) acc[a][b][c] = 0.f;

    // --- ldmatrix per-lane constants ---
    const int lrow = lane&7, grp = lane>>3;
    const uint32_t aBase = (uint32_t)((wm*64 + (grp&1)*8 + lrow)*128);
    const uint32_t bBase = (uint32_t)(STG_B + (wn*64 + (grp>>1)*8 + lrow)*128);
    const int aCsel = grp>>1, bCsel = grp&1;

    for (int kc = 0; kc < 8; kc++){
        if (kc == 7) asm volatile("cp.async.wait_group 0;" ::: "memory");
        else         asm volatile("cp.async.wait_group 1;" ::: "memory");
        __syncthreads();
        if (kc + 2 < 8) issue(kc+2);

        const uint32_t st = sb + (kc%3)*STAGE_SZ;
#pragma unroll
        for (int ks = 0; ks < 4; ks++){
            const uint32_t va = (uint32_t)(((2*ks + aCsel) ^ lrow) << 4);
            const uint32_t vb = (uint32_t)(((2*ks + bCsel) ^ lrow) << 4);
            uint32_t a[4][4], b[8][2];
#pragma unroll
            for (int mt = 0; mt < 4; mt++)
                ldsm4(a[mt], st + aBase + mt*2048 + va);
#pragma unroll
            for (int pr = 0; pr < 4; pr++){
                uint32_t q[4];
                ldsm4(q, st + bBase + pr*2048 + vb);
                b[pr*2][0] = q[0]; b[pr*2][1] = q[1];
                b[pr*2+1][0] = q[2]; b[pr*2+1][1] = q[3];
            }
#pragma unroll
            for (int mt = 0; mt < 4; mt++)
#pragma unroll
                for (int nt = 0; nt < 8; nt++)
                    mma16(acc[mt][nt], a[mt], b[nt]);
        }
    }

    __syncthreads();   // stage smem now free for output staging

    float*  outS  = (float*) smem;   // [128][36] fp32 (padded)
    __half* outSh = (__half*)smem;   // [128][40] fp16 (padded)

#pragma unroll
    for (int mt = 0; mt < 4; mt++){
#pragma unroll
        for (int nt = 0; nt < 8; nt++){
            int rl0 = wm*64 + mt*16 + g;
            int rl1 = rl0 + 8;
            int pl  = wn*64 + nt*8 + 2*t;
            const float2 hbE = *(const float2*)(hhp + (rl0&63)*2048 + ncb + pl);
            const float2 hbO = *(const float2*)(hhp + (rl1&63)*2048 + ncb + pl);
            float d0 = acc[mt][nt][0] + hbE.x;
            float d1 = acc[mt][nt][1] + hbE.y;
            float d2 = acc[mt][nt][2] + hbO.x;
            float d3 = acc[mt][nt][3] + hbO.y;
            float s0 = (t&1) ? d0 : d2;  float r0 = __shfl_xor_sync(0xffffffffu, s0, 1);
            float s1 = (t&1) ? d1 : d3;  float r1 = __shfl_xor_sync(0xffffffffu, s1, 1);
            float ig, fg, gg, og; int rr;
            if (!(t&1)){ ig = d0; fg = d1; gg = r0; og = r1; rr = rl0; }
            else       { ig = r0; fg = r1; gg = d2; og = d3; rr = rl1; }
            int hl = wn*16 + nt*2 + (t>>1);
            float c0v = c0l[(rr&63)*512 + hbase + hl];
            float cy = sigmf(fg)*c0v + sigmf(ig)*tanhf2(gg);
            float hy = sigmf(og)*tanhf2(cy);
            if (outf) outS[rr*36 + hl] = hy;
            else      outSh[rr*40 + hl] = __float2half_rn(hy);
            int grow_ = row0 + rr;
            if (grow_ >= RR - BB){
                int b = grow_ & 63;
                lasth[b*512 + hbase + hl] = hy;
                lastc[b*512 + hbase + hl] = cy;
            }
        }
    }
    __syncthreads();

    if (outf){
#pragma unroll
        for (int i = 0; i < 8; i++){
            int idx = tid + i*128;
            int r = idx >> 3, j = idx & 7;
            float4 v = *(const float4*)(outS + r*36 + j*4);
            *(float4*)(outf + (size_t)(row0+r)*512 + hbase + j*4) = v;
        }
    } else {
#pragma unroll
        for (int i = 0; i < 4; i++){
            int idx = tid + i*128;
            int r = idx >> 2, j = idx & 3;
            uint4 v = *(const uint4*)(outSh + r*40 + j*8);
            *(uint4*)(outh + (size_t)(row0+r)*512 + hbase + j*8) = v;
        }
    }
}

// ---------------- launch ----------------
extern "C" void kernel_launch(void* const* d_in, const int* in_sizes, int n_in,
                              void* d_out, int out_size)
{
    (void)in_sizes; (void)n_in; (void)out_size;
    const float* x    = (const float*)d_in[0];
    const float* h0   = (const float*)d_in[1];
    const float* c0   = (const float*)d_in[2];
    const float* wih0 = (const float*)d_in[3];
    const float* whh0 = (const float*)d_in[4];
    const float* bih0 = (const float*)d_in[5];
    const float* bhh0 = (const float*)d_in[6];
    const float* wih1 = (const float*)d_in[7];
    const float* whh1 = (const float*)d_in[8];
    const float* bih1 = (const float*)d_in[9];
    const float* bhh1 = (const float*)d_in[10];
    float* out = (float*)d_out;

    static __half* xh_p = nullptr; static __half* hy0h_p = nullptr;
    static __half* wp0_p = nullptr; static __half* wp1_p = nullptr;
    static float* hhp0_p = nullptr; static float* hhp1_p = nullptr;
    if (!xh_p){
        cudaGetSymbolAddress((void**)&xh_p,   g_xh);
        cudaGetSymbolAddress((void**)&hy0h_p, g_hy0h);
        void* wp; cudaGetSymbolAddress(&wp, g_wp);
        wp0_p = (__half*)wp; wp1_p = wp0_p + 2048*512;
        void* hh; cudaGetSymbolAddress(&hh, g_hhp);
        hhp0_p = (float*)hh; hhp1_p = hhp0_p + BB*2048;
        cudaFuncSetAttribute(lstm_gemm, cudaFuncAttributeMaxDynamicSharedMemorySize, SMEM_TOT);
    }

    conv_x<<<(RR*32 + 255)/256, 256>>>(x);
    conv_w<<<dim3(256,2), 256>>>(wih0, wih1);
    prep_hh<<<dim3(128,2), 1024>>>(h0, whh0, bhh0, bih0, whh1, bhh1, bih1);

    // layer 0: A = xh, B = wp0 -> hy0h (fp16), lasth[0], lastc[0]
    lstm_gemm<<<dim3(16,512), 128, SMEM_TOT>>>(xh_p, wp0_p, hhp0_p, c0,
                                               nullptr, hy0h_p,
                                               out + RES, out + RES + 2*(size_t)BH);
    // layer 1: A = hy0h, B = wp1 -> out (fp32), lasth[1], lastc[1]
    lstm_gemm<<<dim3(16,512), 128, SMEM_TOT>>>(hy0h_p, wp1_p, hhp1_p, c0 + BH,
                                               out, nullptr,
                                               out + RES + (size_t)BH, out + RES + 3*(size_t)BH);
}

// round 11
// speedup vs baseline: 2.0952x; 1.0342x over previous
#include <cuda_runtime.h>
#include <cuda_fp16.h>
#include <cstdint>

#define TT 1024
#define BB 64
#define HH 512
#define RR (TT*BB)              // 65536 rows
#define RES ((size_t)RR*HH)
#define BH (BB*HH)

// ---------------- device scratch ----------------
__device__ __half g_xh[(size_t)RR*512];      // x in fp16 (natural order)
__device__ __half g_hy0h[(size_t)RR*512];    // layer-0 hy in fp16 (natural order)
__device__ __half g_wp[2][2048*512];         // gate-permuted rows (p=4h+gate), natural k
__device__ float  g_hhp[2][BB*2048];         // h0@Whh^T + b_ih + b_hh, cols p=4h+gate

// ---------------- helpers ----------------
__device__ __forceinline__ uint32_t smem_u32(const void* p){
    uint32_t a; asm("{ .reg .u64 t; cvta.to.shared.u64 t, %1; cvt.u32.u64 %0, t; }" : "=r"(a) : "l"(p)); return a;
}
__device__ __forceinline__ float tanha(float x){ float r; asm("tanh.approx.f32 %0,%1;" : "=f"(r):"f"(x)); return r; }

__device__ __forceinline__ void cpa16(uint32_t dst, const void* src){
    asm volatile("cp.async.cg.shared.global [%0], [%1], 16;" :: "r"(dst), "l"(src) : "memory");
}
#define CP_COMMIT() asm volatile("cp.async.commit_group;" ::: "memory")

__device__ __forceinline__ void mma16(float* c, const uint32_t* a, const uint32_t* b){
    asm volatile("mma.sync.aligned.m16n8k16.row.col.f32.f16.f16.f32 "
                 "{%0,%1,%2,%3}, {%4,%5,%6,%7}, {%8,%9}, {%0,%1,%2,%3};"
                 : "+f"(c[0]),"+f"(c[1]),"+f"(c[2]),"+f"(c[3])
                 : "r"(a[0]),"r"(a[1]),"r"(a[2]),"r"(a[3]), "r"(b[0]),"r"(b[1]));
}
__device__ __forceinline__ void ldsm4(uint32_t* r, uint32_t addr){
    asm volatile("ldmatrix.sync.aligned.m8n8.x4.shared.b16 {%0,%1,%2,%3}, [%4];"
                 : "=r"(r[0]),"=r"(r[1]),"=r"(r[2]),"=r"(r[3]) : "r"(addr));
}
__device__ __forceinline__ uint32_t h2u(const __half2 h){
    union { __half2 h2; uint32_t u; } cv; cv.h2 = h; return cv.u;
}

// natural-order pack: 16 floats -> 16 halves (2 uint4)
__device__ __forceinline__ void pack_nat(const float4 f0, const float4 f1,
                                         const float4 f2, const float4 f3, uint4* o){
    o[0] = make_uint4(h2u(__floats2half2_rn(f0.x,f0.y)), h2u(__floats2half2_rn(f0.z,f0.w)),
                      h2u(__floats2half2_rn(f1.x,f1.y)), h2u(__floats2half2_rn(f1.z,f1.w)));
    o[1] = make_uint4(h2u(__floats2half2_rn(f2.x,f2.y)), h2u(__floats2half2_rn(f2.z,f2.w)),
                      h2u(__floats2half2_rn(f3.x,f3.y)), h2u(__floats2half2_rn(f3.z,f3.w)));
}

// ---------------- prep kernels ----------------
__global__ void conv_x(const float* __restrict__ x){
    int task = blockIdx.x*256 + threadIdx.x;        // row*32 + grp
    if (task >= RR*32) return;
    int row = task >> 5, grp = task & 31;
    const float4* s = (const float4*)(x + (size_t)row*512 + grp*16);
    uint4 o[2];
    pack_nat(s[0], s[1], s[2], s[3], o);
    uint4* d = (uint4*)(g_xh + (size_t)row*512 + grp*16);
    d[0] = o[0]; d[1] = o[1];
}

__global__ void conv_w(const float* __restrict__ wih0, const float* __restrict__ wih1){
    int p = blockIdx.x*8 + (threadIdx.x>>5), l = blockIdx.y, grp = threadIdx.x&31;
    const float* w = l ? wih1 : wih0;
    int grow = ((p&3)<<9) + (p>>2);
    const float4* s = (const float4*)(w + (size_t)grow*512 + grp*16);
    uint4 o[2];
    pack_nat(s[0], s[1], s[2], s[3], o);
    uint4* d = (uint4*)(&g_wp[l][(size_t)p*512 + grp*16]);
    d[0] = o[0]; d[1] = o[1];
}

// tiled: block = 16 p-rows x 64 b; h0 k-slice staged in smem transposed [k][b]
__global__ void __launch_bounds__(1024,1) prep_hh(
        const float* __restrict__ h0,
        const float* __restrict__ whh0, const float* __restrict__ bhh0, const float* __restrict__ bih0,
        const float* __restrict__ whh1, const float* __restrict__ bhh1, const float* __restrict__ bih1){
    __shared__ float sh[128][65];
    int l = blockIdx.y;
    int tid = threadIdx.x;
    int pi = tid >> 6, b = tid & 63;
    int p = blockIdx.x*16 + pi;
    const float* whh = l ? whh1 : whh0;
    const float* bhh = l ? bhh1 : bhh0;
    const float* bih = l ? bih1 : bih0;
    int grow = ((p&3)<<9) + (p>>2);
    const float* wr = whh + (size_t)grow*512;
    float acc = 0.f;
    for (int kb = 0; kb < 4; kb++){
        #pragma unroll
        for (int i = 0; i < 2; i++){
            int f4 = tid*2 + i;                 // 0..2047
            int bb = f4 >> 5, kq = f4 & 31;
            float4 v = *(const float4*)(h0 + (size_t)(l*64+bb)*512 + kb*128 + kq*4);
            sh[kq*4+0][bb] = v.x; sh[kq*4+1][bb] = v.y;
            sh[kq*4+2][bb] = v.z; sh[kq*4+3][bb] = v.w;
        }
        __syncthreads();
        const float4* wv = (const float4*)(wr + kb*128);
        #pragma unroll 8
        for (int k4 = 0; k4 < 32; k4++){
            float4 w = wv[k4];
            acc += w.x*sh[k4*4+0][b] + w.y*sh[k4*4+1][b]
                 + w.z*sh[k4*4+2][b] + w.w*sh[k4*4+3][b];
        }
        __syncthreads();
    }
    g_hhp[l][b*2048 + p] = acc + bhh[grow] + bih[grow];
}

// ---------------- fused GEMM + LSTM epilogue ----------------
// CTA tile 128x128, 4 warps (2m x 2n), warp tile 64x64, K-chunk 64, 3 stages, 2 CTAs/SM
#define STG_B    16384                 // B offset inside a stage (A = 128*128B)
#define STAGE_SZ 32768
#define SMEM_TOT (3*STAGE_SZ)          // 98304

__global__ void __launch_bounds__(128,2)
lstm_gemm(const __half* __restrict__ Ah, const __half* __restrict__ Bh,
          const float* __restrict__ hhp, const float* __restrict__ c0l,
          float* __restrict__ outf, __half* __restrict__ outh,
          float* __restrict__ lasth, float* __restrict__ lastc)
{
    extern __shared__ char smem[];
    const uint32_t sb = smem_u32(smem);
    const int tid = threadIdx.x, wid = tid>>5, lane = tid&31;
    const int g = lane>>2, t = lane&3;
    const int wm = wid&1, wn = wid>>1;          // 2 x 2 warp grid, warp tile 64x64
    const int row0 = blockIdx.y*128, ncb = blockIdx.x*128, hbase = ncb>>2;
    const bool tailCTA = (row0 == RR - 128);

    // --- cp.async per-thread constants (lr covers 0..15; +j*16 rows) ---
    const int lr = tid>>3, lc = tid&7;
    const __half* aSrc = Ah + (size_t)(row0+lr)*512 + lc*8;
    const __half* bSrc = Bh + (size_t)(ncb+lr)*512 + lc*8;
    const uint32_t stOff = (uint32_t)(lr*128 + ((lc ^ (lr&7))<<4));

    auto issue = [&](int kc){
        uint32_t base = sb + (kc%3)*STAGE_SZ + stOff;
        const __half* as = aSrc + kc*64;
        const __half* bs = bSrc + kc*64;
#pragma unroll
        for (int j = 0; j < 8; j++) cpa16(base + j*2048, as + j*(16*512));
#pragma unroll
        for (int j = 0; j < 8; j++) cpa16(base + STG_B + j*2048, bs + j*(16*512));
        CP_COMMIT();
    };

    issue(0); issue(1);

    float acc[4][8][4];
#pragma unroll
    for (int a = 0; a < 4; a++)
#pragma unroll
        for (int b = 0; b < 8; b++)
#pragma unroll
            for (int c = 0; c < 4; c++) acc[a][b][c] = 0.f;

    // --- ldmatrix per-lane constants ---
    const int lrow = lane&7, grp = lane>>3;
    const uint32_t aBase = (uint32_t)((wm*64 + (grp&1)*8 + lrow)*128);
    const uint32_t bBase = (uint32_t)(STG_B + (wn*64 + (grp>>1)*8 + lrow)*128);
    const int aCsel = grp>>1, bCsel = grp&1;

    for (int kc = 0; kc < 8; kc++){
        if (kc == 7) asm volatile("cp.async.wait_group 0;" ::: "memory");
        else         asm volatile("cp.async.wait_group 1;" ::: "memory");
        __syncthreads();
        if (kc + 2 < 8) issue(kc+2);

        const uint32_t st = sb + (kc%3)*STAGE_SZ;
#pragma unroll
        for (int ks = 0; ks < 4; ks++){
            const uint32_t va = (uint32_t)(((2*ks + aCsel) ^ lrow) << 4);
            const uint32_t vb = (uint32_t)(((2*ks + bCsel) ^ lrow) << 4);
            uint32_t a[4][4], b[8][2];
#pragma unroll
            for (int mt = 0; mt < 4; mt++)
                ldsm4(a[mt], st + aBase + mt*2048 + va);
#pragma unroll
            for (int pr = 0; pr < 4; pr++){
                uint32_t q[4];
                ldsm4(q, st + bBase + pr*2048 + vb);
                b[pr*2][0] = q[0]; b[pr*2][1] = q[1];
                b[pr*2+1][0] = q[2]; b[pr*2+1][1] = q[3];
            }
#pragma unroll
            for (int mt = 0; mt < 4; mt++)
#pragma unroll
                for (int nt = 0; nt < 8; nt++)
                    mma16(acc[mt][nt], a[mt], b[nt]);
        }
    }

    __syncthreads();   // stage smem now free for output staging

    float*  outS  = (float*) smem;   // [128][36] fp32 (padded)
    __half* outSh = (__half*)smem;   // [128][40] fp16 (padded)

#pragma unroll
    for (int mt = 0; mt < 4; mt++){
#pragma unroll
        for (int nt = 0; nt < 8; nt++){
            int rl0 = wm*64 + mt*16 + g;
            int rl1 = rl0 + 8;
            int pl  = wn*64 + nt*8 + 2*t;
            const float2 hbE = *(const float2*)(hhp + (rl0&63)*2048 + ncb + pl);
            const float2 hbO = *(const float2*)(hhp + (rl1&63)*2048 + ncb + pl);
            float d0 = acc[mt][nt][0] + hbE.x;
            float d1 = acc[mt][nt][1] + hbE.y;
            float d2 = acc[mt][nt][2] + hbO.x;
            float d3 = acc[mt][nt][3] + hbO.y;
            float s0 = (t&1) ? d0 : d2;  float r0 = __shfl_xor_sync(0xffffffffu, s0, 1);
            float s1 = (t&1) ? d1 : d3;  float r1 = __shfl_xor_sync(0xffffffffu, s1, 1);
            float ig, fg, gg, og; int rr;
            if (!(t&1)){ ig = d0; fg = d1; gg = r0; og = r1; rr = rl0; }
            else       { ig = r0; fg = r1; gg = d2; og = d3; rr = rl1; }
            int hl = wn*16 + nt*2 + (t>>1);
            float c0v = c0l[(rr&63)*512 + hbase + hl];
            // sigmoid(x) = 0.5*(1+tanh(0.5x)); all activations via tanh.approx (1 MUFU each)
            float tf = tanha(0.5f*fg), ti = tanha(0.5f*ig);
            float tg = tanha(gg),      to = tanha(0.5f*og);
            float cy = (0.5f + 0.5f*tf)*c0v + (0.5f + 0.5f*ti)*tg;
            float hy = (0.5f + 0.5f*to)*tanha(cy);
            if (outf) outS[rr*36 + hl] = hy;
            else      outSh[rr*40 + hl] = __float2half_rn(hy);
            if (tailCTA){
                int grow_ = row0 + rr;
                if (grow_ >= RR - BB){
                    int b = grow_ & 63;
                    lasth[b*512 + hbase + hl] = hy;
                    lastc[b*512 + hbase + hl] = cy;
                }
            }
        }
    }
    __syncthreads();

    if (outf){
#pragma unroll
        for (int i = 0; i < 8; i++){
            int idx = tid + i*128;
            int r = idx >> 3, j = idx & 7;
            float4 v = *(const float4*)(outS + r*36 + j*4);
            *(float4*)(outf + (size_t)(row0+r)*512 + hbase + j*4) = v;
        }
    } else {
#pragma unroll
        for (int i = 0; i < 4; i++){
            int idx = tid + i*128;
            int r = idx >> 2, j = idx & 3;
            uint4 v = *(const uint4*)(outSh + r*40 + j*8);
            *(uint4*)(outh + (size_t)(row0+r)*512 + hbase + j*8) = v;
        }
    }
}

// ---------------- launch ----------------
extern "C" void kernel_launch(void* const* d_in, const int* in_sizes, int n_in,
                              void* d_out, int out_size)
{
    (void)in_sizes; (void)n_in; (void)out_size;
    const float* x    = (const float*)d_in[0];
    const float* h0   = (const float*)d_in[1];
    const float* c0   = (const float*)d_in[2];
    const float* wih0 = (const float*)d_in[3];
    const float* whh0 = (const float*)d_in[4];
    const float* bih0 = (const float*)d_in[5];
    const float* bhh0 = (const float*)d_in[6];
    const float* wih1 = (const float*)d_in[7];
    const float* whh1 = (const float*)d_in[8];
    const float* bih1 = (const float*)d_in[9];
    const float* bhh1 = (const float*)d_in[10];
    float* out = (float*)d_out;

    static __half* xh_p = nullptr; static __half* hy0h_p = nullptr;
    static __half* wp0_p = nullptr; static __half* wp1_p = nullptr;
    static float* hhp0_p = nullptr; static float* hhp1_p = nullptr;
    if (!xh_p){
        cudaGetSymbolAddress((void**)&xh_p,   g_xh);
        cudaGetSymbolAddress((void**)&hy0h_p, g_hy0h);
        void* wp; cudaGetSymbolAddress(&wp, g_wp);
        wp0_p = (__half*)wp; wp1_p = wp0_p + 2048*512;
        void* hh; cudaGetSymbolAddress(&hh, g_hhp);
        hhp0_p = (float*)hh; hhp1_p = hhp0_p + BB*2048;
        cudaFuncSetAttribute(lstm_gemm, cudaFuncAttributeMaxDynamicSharedMemorySize, SMEM_TOT);
    }

    conv_x<<<(RR*32 + 255)/256, 256>>>(x);
    conv_w<<<dim3(256,2), 256>>>(wih0, wih1);
    prep_hh<<<dim3(128,2), 1024>>>(h0, whh0, bhh0, bih0, whh1, bhh1, bih1);

    // layer 0: A = xh, B = wp0 -> hy0h (fp16), lasth[0], lastc[0]
    lstm_gemm<<<dim3(16,512), 128, SMEM_TOT>>>(xh_p, wp0_p, hhp0_p, c0,
                                               nullptr, hy0h_p,
                                               out + RES, out + RES + 2*(size_t)BH);
    // layer 1: A = hy0h, B = wp1 -> out (fp32), lasth[1], lastc[1]
    lstm_gemm<<<dim3(16,512), 128, SMEM_TOT>>>(hy0h_p, wp1_p, hhp1_p, c0 + BH,
                                               out, nullptr,
                                               out + RES + (size_t)BH, out + RES + 3*(size_t)BH);
}

// round 12
// speedup vs baseline: 2.1257x; 1.0145x over previous
#include <cuda_runtime.h>
#include <cuda_fp16.h>
#include <cstdint>

#define TT 1024
#define BB 64
#define HH 512
#define RR (TT*BB)              // 65536 rows
#define RES ((size_t)RR*HH)
#define BH (BB*HH)

// ---------------- device scratch ----------------
__device__ __half g_xh[(size_t)RR*512];      // x in fp16 (natural order)
__device__ __half g_hy0h[(size_t)RR*512];    // layer-0 hy in fp16 (natural order)
__device__ __half g_wp[2][2048*512];         // gate-permuted rows (p=4h+gate), natural k
__device__ float  g_hhp[2][BB*2048];         // h0@Whh^T + b_ih + b_hh, cols p=4h+gate

// ---------------- helpers ----------------
__device__ __forceinline__ uint32_t smem_u32(const void* p){
    uint32_t a; asm("{ .reg .u64 t; cvta.to.shared.u64 t, %1; cvt.u32.u64 %0, t; }" : "=r"(a) : "l"(p)); return a;
}
__device__ __forceinline__ float tanha(float x){ float r; asm("tanh.approx.f32 %0,%1;" : "=f"(r):"f"(x)); return r; }

__device__ __forceinline__ void cpa16(uint32_t dst, const void* src){
    asm volatile("cp.async.cg.shared.global [%0], [%1], 16;" :: "r"(dst), "l"(src) : "memory");
}
#define CP_COMMIT() asm volatile("cp.async.commit_group;" ::: "memory")

__device__ __forceinline__ void mma16(float* c, const uint32_t* a, const uint32_t* b){
    asm volatile("mma.sync.aligned.m16n8k16.row.col.f32.f16.f16.f32 "
                 "{%0,%1,%2,%3}, {%4,%5,%6,%7}, {%8,%9}, {%0,%1,%2,%3};"
                 : "+f"(c[0]),"+f"(c[1]),"+f"(c[2]),"+f"(c[3])
                 : "r"(a[0]),"r"(a[1]),"r"(a[2]),"r"(a[3]), "r"(b[0]),"r"(b[1]));
}
__device__ __forceinline__ void ldsm4(uint32_t* r, uint32_t addr){
    asm volatile("ldmatrix.sync.aligned.m8n8.x4.shared.b16 {%0,%1,%2,%3}, [%4];"
                 : "=r"(r[0]),"=r"(r[1]),"=r"(r[2]),"=r"(r[3]) : "r"(addr));
}
__device__ __forceinline__ uint32_t h2u(const __half2 h){
    union { __half2 h2; uint32_t u; } cv; cv.h2 = h; return cv.u;
}

// natural-order pack: 16 floats -> 16 halves (2 uint4)
__device__ __forceinline__ void pack_nat(const float4 f0, const float4 f1,
                                         const float4 f2, const float4 f3, uint4* o){
    o[0] = make_uint4(h2u(__floats2half2_rn(f0.x,f0.y)), h2u(__floats2half2_rn(f0.z,f0.w)),
                      h2u(__floats2half2_rn(f1.x,f1.y)), h2u(__floats2half2_rn(f1.z,f1.w)));
    o[1] = make_uint4(h2u(__floats2half2_rn(f2.x,f2.y)), h2u(__floats2half2_rn(f2.z,f2.w)),
                      h2u(__floats2half2_rn(f3.x,f3.y)), h2u(__floats2half2_rn(f3.z,f3.w)));
}

// ---------------- prep kernels ----------------
__global__ void conv_x(const float* __restrict__ x){
    int task = blockIdx.x*256 + threadIdx.x;        // row*32 + grp
    if (task >= RR*32) return;
    int row = task >> 5, grp = task & 31;
    const float4* s = (const float4*)(x + (size_t)row*512 + grp*16);
    uint4 o[2];
    pack_nat(s[0], s[1], s[2], s[3], o);
    uint4* d = (uint4*)(g_xh + (size_t)row*512 + grp*16);
    d[0] = o[0]; d[1] = o[1];
}

__global__ void conv_w(const float* __restrict__ wih0, const float* __restrict__ wih1){
    int p = blockIdx.x*8 + (threadIdx.x>>5), l = blockIdx.y, grp = threadIdx.x&31;
    const float* w = l ? wih1 : wih0;
    int grow = ((p&3)<<9) + (p>>2);
    const float4* s = (const float4*)(w + (size_t)grow*512 + grp*16);
    uint4 o[2];
    pack_nat(s[0], s[1], s[2], s[3], o);
    uint4* d = (uint4*)(&g_wp[l][(size_t)p*512 + grp*16]);
    d[0] = o[0]; d[1] = o[1];
}

// tiled: block = 16 p-rows x 64 b; h0 k-slice staged in smem transposed [k][b]
__global__ void __launch_bounds__(1024,1) prep_hh(
        const float* __restrict__ h0,
        const float* __restrict__ whh0, const float* __restrict__ bhh0, const float* __restrict__ bih0,
        const float* __restrict__ whh1, const float* __restrict__ bhh1, const float* __restrict__ bih1){
    __shared__ float sh[128][65];
    int l = blockIdx.y;
    int tid = threadIdx.x;
    int pi = tid >> 6, b = tid & 63;
    int p = blockIdx.x*16 + pi;
    const float* whh = l ? whh1 : whh0;
    const float* bhh = l ? bhh1 : bhh0;
    const float* bih = l ? bih1 : bih0;
    int grow = ((p&3)<<9) + (p>>2);
    const float* wr = whh + (size_t)grow*512;
    float acc = 0.f;
    for (int kb = 0; kb < 4; kb++){
        #pragma unroll
        for (int i = 0; i < 2; i++){
            int f4 = tid*2 + i;                 // 0..2047
            int bb = f4 >> 5, kq = f4 & 31;
            float4 v = *(const float4*)(h0 + (size_t)(l*64+bb)*512 + kb*128 + kq*4);
            sh[kq*4+0][bb] = v.x; sh[kq*4+1][bb] = v.y;
            sh[kq*4+2][bb] = v.z; sh[kq*4+3][bb] = v.w;
        }
        __syncthreads();
        const float4* wv = (const float4*)(wr + kb*128);
        #pragma unroll 8
        for (int k4 = 0; k4 < 32; k4++){
            float4 w = wv[k4];
            acc += w.x*sh[k4*4+0][b] + w.y*sh[k4*4+1][b]
                 + w.z*sh[k4*4+2][b] + w.w*sh[k4*4+3][b];
        }
        __syncthreads();
    }
    g_hhp[l][b*2048 + p] = acc + bhh[grow] + bih[grow];
}

// ---------------- fused GEMM + LSTM epilogue ----------------
// CTA tile 128x128, 4 warps (2m x 2n), warp tile 64x64, K-chunk 64, 3 stages, 2 CTAs/SM
// Register-level fragment double-buffering across ks steps.
#define STG_B    16384                 // B offset inside a stage (A = 128*128B)
#define STAGE_SZ 32768
#define SMEM_TOT (3*STAGE_SZ)          // 98304

__global__ void __launch_bounds__(128,2)
lstm_gemm(const __half* __restrict__ Ah, const __half* __restrict__ Bh,
          const float* __restrict__ hhp, const float* __restrict__ c0l,
          float* __restrict__ outf, __half* __restrict__ outh,
          float* __restrict__ lasth, float* __restrict__ lastc)
{
    extern __shared__ char smem[];
    const uint32_t sb = smem_u32(smem);
    const int tid = threadIdx.x, wid = tid>>5, lane = tid&31;
    const int g = lane>>2, t = lane&3;
    const int wm = wid&1, wn = wid>>1;          // 2 x 2 warp grid, warp tile 64x64
    const int row0 = blockIdx.y*128, ncb = blockIdx.x*128, hbase = ncb>>2;
    const bool tailCTA = (row0 == RR - 128);

    // --- cp.async per-thread constants (lr covers 0..15; +j*16 rows) ---
    const int lr = tid>>3, lc = tid&7;
    const __half* aSrc = Ah + (size_t)(row0+lr)*512 + lc*8;
    const __half* bSrc = Bh + (size_t)(ncb+lr)*512 + lc*8;
    const uint32_t stOff = (uint32_t)(lr*128 + ((lc ^ (lr&7))<<4));

    auto issue = [&](int kc){
        uint32_t base = sb + (kc%3)*STAGE_SZ + stOff;
        const __half* as = aSrc + kc*64;
        const __half* bs = bSrc + kc*64;
#pragma unroll
        for (int j = 0; j < 8; j++) cpa16(base + j*2048, as + j*(16*512));
#pragma unroll
        for (int j = 0; j < 8; j++) cpa16(base + STG_B + j*2048, bs + j*(16*512));
        CP_COMMIT();
    };

    issue(0); issue(1);

    float acc[4][8][4];
#pragma unroll
    for (int a = 0; a < 4; a++)
#pragma unroll
        for (int b = 0; b < 8; b++)
#pragma unroll
            for (int c = 0; c < 4; c++) acc[a][b][c] = 0.f;

    // --- ldmatrix per-lane constants ---
    const int lrow = lane&7, grp = lane>>3;
    const uint32_t aBase = (uint32_t)((wm*64 + (grp&1)*8 + lrow)*128);
    const uint32_t bBase = (uint32_t)(STG_B + (wn*64 + (grp>>1)*8 + lrow)*128);
    const int aCsel = grp>>1, bCsel = grp&1;

    // fragment double buffers
    uint32_t Af[2][4][4], Bf[2][8][2];

    auto load_frags = [&](uint32_t st, int ks, int buf){
        const uint32_t va = (uint32_t)(((2*ks + aCsel) ^ lrow) << 4);
        const uint32_t vb = (uint32_t)(((2*ks + bCsel) ^ lrow) << 4);
#pragma unroll
        for (int mt = 0; mt < 4; mt++)
            ldsm4(Af[buf][mt], st + aBase + mt*2048 + va);
#pragma unroll
        for (int pr = 0; pr < 4; pr++){
            uint32_t q[4];
            ldsm4(q, st + bBase + pr*2048 + vb);
            Bf[buf][pr*2][0] = q[0]; Bf[buf][pr*2][1] = q[1];
            Bf[buf][pr*2+1][0] = q[2]; Bf[buf][pr*2+1][1] = q[3];
        }
    };

    for (int kc = 0; kc < 8; kc++){
        if (kc == 7) asm volatile("cp.async.wait_group 0;" ::: "memory");
        else         asm volatile("cp.async.wait_group 1;" ::: "memory");
        __syncthreads();
        if (kc + 2 < 8) issue(kc+2);

        const uint32_t st = sb + (kc%3)*STAGE_SZ;
        load_frags(st, 0, 0);
#pragma unroll
        for (int ks = 0; ks < 4; ks++){
            const int cur = ks & 1;
            if (ks < 3) load_frags(st, ks+1, cur^1);
#pragma unroll
            for (int mt = 0; mt < 4; mt++)
#pragma unroll
                for (int nt = 0; nt < 8; nt++)
                    mma16(acc[mt][nt], Af[cur][mt], Bf[cur][nt]);
        }
    }

    __syncthreads();   // stage smem now free for output staging

    float*  outS  = (float*) smem;   // [128][36] fp32 (padded)
    __half* outSh = (__half*)smem;   // [128][40] fp16 (padded)

#pragma unroll
    for (int mt = 0; mt < 4; mt++){
#pragma unroll
        for (int nt = 0; nt < 8; nt++){
            int rl0 = wm*64 + mt*16 + g;
            int rl1 = rl0 + 8;
            int pl  = wn*64 + nt*8 + 2*t;
            const float2 hbE = *(const float2*)(hhp + (rl0&63)*2048 + ncb + pl);
            const float2 hbO = *(const float2*)(hhp + (rl1&63)*2048 + ncb + pl);
            float d0 = acc[mt][nt][0] + hbE.x;
            float d1 = acc[mt][nt][1] + hbE.y;
            float d2 = acc[mt][nt][2] + hbO.x;
            float d3 = acc[mt][nt][3] + hbO.y;
            float s0 = (t&1) ? d0 : d2;  float r0 = __shfl_xor_sync(0xffffffffu, s0, 1);
            float s1 = (t&1) ? d1 : d3;  float r1 = __shfl_xor_sync(0xffffffffu, s1, 1);
            float ig, fg, gg, og; int rr;
            if (!(t&1)){ ig = d0; fg = d1; gg = r0; og = r1; rr = rl0; }
            else       { ig = r0; fg = r1; gg = d2; og = d3; rr = rl1; }
            int hl = wn*16 + nt*2 + (t>>1);
            float c0v = c0l[(rr&63)*512 + hbase + hl];
            // sigmoid(x) = 0.5*(1+tanh(0.5x)); all activations via tanh.approx
            float tf = tanha(0.5f*fg), ti = tanha(0.5f*ig);
            float tg = tanha(gg),      to = tanha(0.5f*og);
            float cy = (0.5f + 0.5f*tf)*c0v + (0.5f + 0.5f*ti)*tg;
            float hy = (0.5f + 0.5f*to)*tanha(cy);
            if (outf) outS[rr*36 + hl] = hy;
            else      outSh[rr*40 + hl] = __float2half_rn(hy);
            if (tailCTA){
                int grow_ = row0 + rr;
                if (grow_ >= RR - BB){
                    int b = grow_ & 63;
                    lasth[b*512 + hbase + hl] = hy;
                    lastc[b*512 + hbase + hl] = cy;
                }
            }
        }
    }
    __syncthreads();

    if (outf){
#pragma unroll
        for (int i = 0; i < 8; i++){
            int idx = tid + i*128;
            int r = idx >> 3, j = idx & 7;
            float4 v = *(const float4*)(outS + r*36 + j*4);
            *(float4*)(outf + (size_t)(row0+r)*512 + hbase + j*4) = v;
        }
    } else {
#pragma unroll
        for (int i = 0; i < 4; i++){
            int idx = tid + i*128;
            int r = idx >> 2, j = idx & 3;
            uint4 v = *(const uint4*)(outSh + r*40 + j*8);
            *(uint4*)(outh + (size_t)(row0+r)*512 + hbase + j*8) = v;
        }
    }
}

// ---------------- launch ----------------
extern "C" void kernel_launch(void* const* d_in, const int* in_sizes, int n_in,
                              void* d_out, int out_size)
{
    (void)in_sizes; (void)n_in; (void)out_size;
    const float* x    = (const float*)d_in[0];
    const float* h0   = (const float*)d_in[1];
    const float* c0   = (const float*)d_in[2];
    const float* wih0 = (const float*)d_in[3];
    const float* whh0 = (const float*)d_in[4];
    const float* bih0 = (const float*)d_in[5];
    const float* bhh0 = (const float*)d_in[6];
    const float* wih1 = (const float*)d_in[7];
    const float* whh1 = (const float*)d_in[8];
    const float* bih1 = (const float*)d_in[9];
    const float* bhh1 = (const float*)d_in[10];
    float* out = (float*)d_out;

    static __half* xh_p = nullptr; static __half* hy0h_p = nullptr;
    static __half* wp0_p = nullptr; static __half* wp1_p = nullptr;
    static float* hhp0_p = nullptr; static float* hhp1_p = nullptr;
    if (!xh_p){
        cudaGetSymbolAddress((void**)&xh_p,   g_xh);
        cudaGetSymbolAddress((void**)&hy0h_p, g_hy0h);
        void* wp; cudaGetSymbolAddress(&wp, g_wp);
        wp0_p = (__half*)wp; wp1_p = wp0_p + 2048*512;
        void* hh; cudaGetSymbolAddress(&hh, g_hhp);
        hhp0_p = (float*)hh; hhp1_p = hhp0_p + BB*2048;
        cudaFuncSetAttribute(lstm_gemm, cudaFuncAttributeMaxDynamicSharedMemorySize, SMEM_TOT);
    }

    conv_x<<<(RR*32 + 255)/256, 256>>>(x);
    conv_w<<<dim3(256,2), 256>>>(wih0, wih1);
    prep_hh<<<dim3(128,2), 1024>>>(h0, whh0, bhh0, bih0, whh1, bhh1, bih1);

    // layer 0: A = xh, B = wp0 -> hy0h (fp16), lasth[0], lastc[0]
    lstm_gemm<<<dim3(16,512), 128, SMEM_TOT>>>(xh_p, wp0_p, hhp0_p, c0,
                                               nullptr, hy0h_p,
                                               out + RES, out + RES + 2*(size_t)BH);
    // layer 1: A = hy0h, B = wp1 -> out (fp32), lasth[1], lastc[1]
    lstm_gemm<<<dim3(16,512), 128, SMEM_TOT>>>(hy0h_p, wp1_p, hhp1_p, c0 + BH,
                                               out, nullptr,
                                               out + RES + (size_t)BH, out + RES + 3*(size_t)BH);
}